// round 4
// baseline (speedup 1.0000x reference)
#include <cuda_runtime.h>

// TransOp_expm via Cayley-Hamilton scalarization, 4 batches/thread
// (2 independent f32x2 chains for ILP). NSQ=4, ORDER=8.

#define NSQ 4
#define NORD 8

typedef unsigned long long ull;

__device__ __forceinline__ ull pk(float lo, float hi) {
    ull r; asm("mov.b64 %0, {%1, %2};" : "=l"(r) : "f"(lo), "f"(hi)); return r;
}
__device__ __forceinline__ void upk(ull v, float& lo, float& hi) {
    asm("mov.b64 {%0, %1}, %2;" : "=f"(lo), "=f"(hi) : "l"(v));
}
__device__ __forceinline__ ull fma2(ull a, ull b, ull c) {
    ull d; asm("fma.rn.f32x2 %0, %1, %2, %3;" : "=l"(d) : "l"(a), "l"(b), "l"(c)); return d;
}
__device__ __forceinline__ ull mul2(ull a, ull b) {
    ull d; asm("mul.rn.f32x2 %0, %1, %2;" : "=l"(d) : "l"(a), "l"(b)); return d;
}
__device__ __forceinline__ ull add2(ull a, ull b) {
    ull d; asm("add.rn.f32x2 %0, %1, %2;" : "=l"(d) : "l"(a), "l"(b)); return d;
}

// One packed chain: 2 batches. cm[6] packed coefficients, v* packed x.
// Produces packed y*.
__device__ __forceinline__ void expm_chain(
    const ull* __restrict__ spsi,
    const ull cm[6], ull v0, ull v1, ull v2,
    ull& y0, ull& y1, ull& y2)
{
    const ull NEG1 = pk(-1.0f, -1.0f);
    const ull HALF = pk(0.5f, 0.5f);
    const ull ONE  = pk(1.0f, 1.0f);

    // A = sum_m cm * psi_scaled[m]
    ull A[9];
    #pragma unroll
    for (int j = 0; j < 9; j++) A[j] = mul2(cm[0], spsi[j]);
    #pragma unroll
    for (int m = 1; m < 6; m++) {
        #pragma unroll
        for (int j = 0; j < 9; j++)
            A[j] = fma2(cm[m], spsi[m * 9 + j], A[j]);
    }

    // invariants
    ull c1 = add2(add2(A[0], A[4]), A[8]);
    ull d0 = fma2(A[0], A[0], fma2(A[1], A[3], mul2(A[2], A[6])));
    ull d1 = fma2(A[3], A[1], fma2(A[4], A[4], mul2(A[5], A[7])));
    ull d2 = fma2(A[6], A[2], fma2(A[7], A[5], mul2(A[8], A[8])));
    ull trA2 = add2(add2(d0, d1), d2);
    ull c1sq = mul2(c1, c1);
    ull nc2  = mul2(fma2(c1sq, NEG1, trA2), HALF);          // -c2
    ull m0   = fma2(mul2(A[5], A[7]), NEG1, mul2(A[4], A[8]));
    ull m1n  = fma2(mul2(A[3], A[8]), NEG1, mul2(A[5], A[6]));
    ull m2   = fma2(mul2(A[4], A[6]), NEG1, mul2(A[3], A[7]));
    ull c3   = fma2(A[0], m0, fma2(A[1], m1n, mul2(A[2], m2)));
    ull k_a  = mul2(c1, c3);
    ull k_b  = fma2(c1, nc2, c3);
    ull k_c  = add2(c1sq, nc2);

    // scalar Taylor: E = sa I + sb A + sc A^2
    ull sa = ONE, sb = ONE, sc = HALF;
    ull xk = 0ULL, yk = 0ULL, zk = ONE;
    const float invfact[NORD + 1] = {
        1.f, 1.f, 0.5f,
        1.f/6.f, 1.f/24.f, 1.f/120.f, 1.f/720.f, 1.f/5040.f, 1.f/40320.f
    };
    #pragma unroll
    for (int k = 3; k <= NORD; k++) {
        ull xn = mul2(c3, zk);
        ull yn = fma2(nc2, zk, xk);
        ull zn = fma2(c1, zk, yk);
        ull cf = pk(invfact[k], invfact[k]);
        sa = fma2(xn, cf, sa);
        sb = fma2(yn, cf, sb);
        sc = fma2(zn, cf, sc);
        xk = xn; yk = yn; zk = zn;
    }

    // squarings in coefficient space
    #pragma unroll
    for (int sq = 0; sq < NSQ; sq++) {
        ull t_aa = mul2(sa, sa);
        ull t_bb = mul2(sb, sb);
        ull t_cc = mul2(sc, sc);
        ull t_ab = mul2(sa, sb);
        ull t_ac = mul2(sa, sc);
        ull t_bc = mul2(sb, sc);
        ull t2ab = add2(t_ab, t_ab);
        ull t2ac = add2(t_ac, t_ac);
        ull t2bc = add2(t_bc, t_bc);
        ull na = fma2(t_cc, k_a, fma2(t2bc, c3,  t_aa));
        ull nb = fma2(t_cc, k_b, fma2(t2bc, nc2, t2ab));
        ull nc = fma2(t_cc, k_c, fma2(t2bc, c1,  add2(t_bb, t2ac)));
        sa = na; sb = nb; sc = nc;
    }

    // y = sa*x + sb*(A x) + sc*(A (A x))
    ull w0 = fma2(A[0], v0, fma2(A[1], v1, mul2(A[2], v2)));
    ull w1 = fma2(A[3], v0, fma2(A[4], v1, mul2(A[5], v2)));
    ull w2 = fma2(A[6], v0, fma2(A[7], v1, mul2(A[8], v2)));
    ull u0 = fma2(A[0], w0, fma2(A[1], w1, mul2(A[2], w2)));
    ull u1 = fma2(A[3], w0, fma2(A[4], w1, mul2(A[5], w2)));
    ull u2 = fma2(A[6], w0, fma2(A[7], w1, mul2(A[8], w2)));
    y0 = fma2(sa, v0, fma2(sb, w0, mul2(sc, u0)));
    y1 = fma2(sa, v1, fma2(sb, w1, mul2(sc, u1)));
    y2 = fma2(sa, v2, fma2(sb, w2, mul2(sc, u2)));
}

__global__ __launch_bounds__(128) void expmch4_kernel(
    const float* __restrict__ x,
    const float* __restrict__ c,
    const float* __restrict__ psi,
    float* __restrict__ out,
    int B)
{
    __shared__ ull s_psi2[54];
    if (threadIdx.x < 54) {
        float v = psi[threadIdx.x] * (1.0f / (float)(1 << NSQ));
        s_psi2[threadIdx.x] = pk(v, v);
    }
    __syncthreads();

    int t  = blockIdx.x * blockDim.x + threadIdx.x;
    int b0 = 4 * t;
    if (b0 >= B) return;

    if (b0 + 3 < B) {
        // ---- main path: 4 batches, two independent packed chains ----
        const float4* cq = (const float4*)(c + b0 * 6);
        float4 q0 = __ldg(&cq[0]);
        float4 q1 = __ldg(&cq[1]);
        float4 q2 = __ldg(&cq[2]);
        float4 q3 = __ldg(&cq[3]);
        float4 q4 = __ldg(&cq[4]);
        float4 q5 = __ldg(&cq[5]);

        ull cmA[6], cmB[6];
        // chain A: batches b0 (lo), b0+1 (hi)
        cmA[0] = pk(q0.x, q1.z);
        cmA[1] = pk(q0.y, q1.w);
        cmA[2] = pk(q0.z, q2.x);
        cmA[3] = pk(q0.w, q2.y);
        cmA[4] = pk(q1.x, q2.z);
        cmA[5] = pk(q1.y, q2.w);
        // chain B: batches b0+2 (lo), b0+3 (hi)
        cmB[0] = pk(q3.x, q4.z);
        cmB[1] = pk(q3.y, q4.w);
        cmB[2] = pk(q3.z, q5.x);
        cmB[3] = pk(q3.w, q5.y);
        cmB[4] = pk(q4.x, q5.z);
        cmB[5] = pk(q4.y, q5.w);

        const float4* xq = (const float4*)(x + b0 * 3);
        float4 r0 = __ldg(&xq[0]);  // x0b0 x1b0 x2b0 x0b1
        float4 r1 = __ldg(&xq[1]);  // x1b1 x2b1 x0b2 x1b2
        float4 r2 = __ldg(&xq[2]);  // x2b2 x0b3 x1b3 x2b3

        ull vA0 = pk(r0.x, r0.w);
        ull vA1 = pk(r0.y, r1.x);
        ull vA2 = pk(r0.z, r1.y);
        ull vB0 = pk(r1.z, r2.y);
        ull vB1 = pk(r1.w, r2.z);
        ull vB2 = pk(r2.x, r2.w);

        ull yA0, yA1, yA2, yB0, yB1, yB2;
        expm_chain(s_psi2, cmA, vA0, vA1, vA2, yA0, yA1, yA2);
        expm_chain(s_psi2, cmB, vB0, vB1, vB2, yB0, yB1, yB2);

        float a0l, a0h, a1l, a1h, a2l, a2h;
        float b0l, b0h, b1l, b1h, b2l, b2h;
        upk(yA0, a0l, a0h); upk(yA1, a1l, a1h); upk(yA2, a2l, a2h);
        upk(yB0, b0l, b0h); upk(yB1, b1l, b1h); upk(yB2, b2l, b2h);

        float4* oq = (float4*)(out + b0 * 3);
        oq[0] = make_float4(a0l, a1l, a2l, a0h);
        oq[1] = make_float4(a1h, a2h, b0l, b1l);
        oq[2] = make_float4(b2l, b0h, b1h, b2h);
    } else {
        // ---- tail: up to 3 leftover batches, one (duplicated-lane) chain each ----
        for (int b = b0; b < B; b++) {
            const float* cb = c + b * 6;
            ull cm[6];
            #pragma unroll
            for (int m = 0; m < 6; m++) { float v = __ldg(&cb[m]); cm[m] = pk(v, v); }
            const float* xb = x + b * 3;
            float x0 = __ldg(&xb[0]), x1 = __ldg(&xb[1]), x2 = __ldg(&xb[2]);
            ull y0, y1, y2;
            expm_chain(s_psi2, cm, pk(x0, x0), pk(x1, x1), pk(x2, x2), y0, y1, y2);
            float lo, hi;
            float* ob = out + b * 3;
            upk(y0, lo, hi); ob[0] = lo;
            upk(y1, lo, hi); ob[1] = lo;
            upk(y2, lo, hi); ob[2] = lo;
        }
    }
}

extern "C" void kernel_launch(void* const* d_in, const int* in_sizes, int n_in,
                              void* d_out, int out_size) {
    const float* x   = (const float*)d_in[0];  // [B,3,1]
    const float* c   = (const float*)d_in[1];  // [B,6]
    const float* psi = (const float*)d_in[2];  // [6,3,3]
    float* out = (float*)d_out;                // [B,3]

    int B = in_sizes[0] / 3;
    int quads = (B + 3) / 4;
    int threads = 128;
    int blocks = (quads + threads - 1) / threads;
    expmch4_kernel<<<blocks, threads>>>(x, c, psi, out, B);
}

// round 5
// speedup vs baseline: 1.2326x; 1.2326x over previous
#include <cuda_runtime.h>

// TransOp_expm via Cayley-Hamilton, 2 batches/thread packed f32x2.
// Horner-in-coefficient-space Taylor (state = 3 scalars), matvecs hoisted
// so A is dead during the serial chain. NSQ=4, ORDER=8.

#define NSQ 4
#define NORD 8

typedef unsigned long long ull;

__device__ __forceinline__ ull pk(float lo, float hi) {
    ull r; asm("mov.b64 %0, {%1, %2};" : "=l"(r) : "f"(lo), "f"(hi)); return r;
}
__device__ __forceinline__ void upk(ull v, float& lo, float& hi) {
    asm("mov.b64 {%0, %1}, %2;" : "=f"(lo), "=f"(hi) : "l"(v));
}
__device__ __forceinline__ ull fma2(ull a, ull b, ull c) {
    ull d; asm("fma.rn.f32x2 %0, %1, %2, %3;" : "=l"(d) : "l"(a), "l"(b), "l"(c)); return d;
}
__device__ __forceinline__ ull mul2(ull a, ull b) {
    ull d; asm("mul.rn.f32x2 %0, %1, %2;" : "=l"(d) : "l"(a), "l"(b)); return d;
}
__device__ __forceinline__ ull add2(ull a, ull b) {
    ull d; asm("add.rn.f32x2 %0, %1, %2;" : "=l"(d) : "l"(a), "l"(b)); return d;
}
__device__ __forceinline__ ull bcast(float v) { return pk(v, v); }

__global__ __launch_bounds__(256, 6) void expmch5_kernel(
    const float* __restrict__ x,
    const float* __restrict__ c,
    const float* __restrict__ psi,
    float* __restrict__ out,
    int B)
{
    __shared__ ull s_psi2[54];
    if (threadIdx.x < 54) {
        float v = psi[threadIdx.x] * (1.0f / (float)(1 << NSQ));
        s_psi2[threadIdx.x] = pk(v, v);
    }
    __syncthreads();

    int t  = blockIdx.x * blockDim.x + threadIdx.x;
    int b0 = 2 * t;
    if (b0 >= B) return;
    bool full = (b0 + 1 < B);

    // ---- load c and x early (hide DRAM latency) ----
    ull cm[6];
    ull v0, v1, v2;
    if (full) {
        const float4* cq = (const float4*)(c + b0 * 6);
        float4 q0 = __ldg(&cq[0]);
        float4 q1 = __ldg(&cq[1]);
        float4 q2 = __ldg(&cq[2]);
        const float2* xq = (const float2*)(x + b0 * 3);
        float2 f0 = __ldg(&xq[0]);
        float2 f1 = __ldg(&xq[1]);
        float2 f2 = __ldg(&xq[2]);
        cm[0] = pk(q0.x, q1.z);
        cm[1] = pk(q0.y, q1.w);
        cm[2] = pk(q0.z, q2.x);
        cm[3] = pk(q0.w, q2.y);
        cm[4] = pk(q1.x, q2.z);
        cm[5] = pk(q1.y, q2.w);
        v0 = pk(f0.x, f1.y);
        v1 = pk(f0.y, f2.x);
        v2 = pk(f1.x, f2.y);
    } else {
        const float* cb = c + b0 * 6;
        #pragma unroll
        for (int m = 0; m < 6; m++) { float v = __ldg(&cb[m]); cm[m] = pk(v, v); }
        const float* xb = x + b0 * 3;
        float x0 = __ldg(&xb[0]), x1 = __ldg(&xb[1]), x2 = __ldg(&xb[2]);
        v0 = pk(x0, x0); v1 = pk(x1, x1); v2 = pk(x2, x2);
    }

    // ---- invariants + matvecs in a scope so A's registers die here ----
    ull c1, nc2, c3, k_a, k_b, k_c;     // invariants
    ull w0, w1, w2, u0, u1, u2;         // A x, A^2 x
    {
        const ull NEG1 = bcast(-1.0f);
        ull A[9];
        #pragma unroll
        for (int j = 0; j < 9; j++) A[j] = mul2(cm[0], s_psi2[j]);
        #pragma unroll
        for (int m = 1; m < 6; m++) {
            #pragma unroll
            for (int j = 0; j < 9; j++)
                A[j] = fma2(cm[m], s_psi2[m * 9 + j], A[j]);
        }

        c1 = add2(add2(A[0], A[4]), A[8]);
        ull d0 = fma2(A[0], A[0], fma2(A[1], A[3], mul2(A[2], A[6])));
        ull d1 = fma2(A[3], A[1], fma2(A[4], A[4], mul2(A[5], A[7])));
        ull d2 = fma2(A[6], A[2], fma2(A[7], A[5], mul2(A[8], A[8])));
        ull trA2 = add2(add2(d0, d1), d2);
        ull c1sq = mul2(c1, c1);
        nc2 = mul2(fma2(c1sq, NEG1, trA2), bcast(0.5f));            // -c2
        ull m0  = fma2(mul2(A[5], A[7]), NEG1, mul2(A[4], A[8]));
        ull m1n = fma2(mul2(A[3], A[8]), NEG1, mul2(A[5], A[6]));
        ull m2  = fma2(mul2(A[4], A[6]), NEG1, mul2(A[3], A[7]));
        c3  = fma2(A[0], m0, fma2(A[1], m1n, mul2(A[2], m2)));
        k_a = mul2(c1, c3);
        k_b = fma2(c1, nc2, c3);          // c3 - c1 c2
        k_c = add2(c1sq, nc2);            // c1^2 - c2

        w0 = fma2(A[0], v0, fma2(A[1], v1, mul2(A[2], v2)));
        w1 = fma2(A[3], v0, fma2(A[4], v1, mul2(A[5], v2)));
        w2 = fma2(A[6], v0, fma2(A[7], v1, mul2(A[8], v2)));
        u0 = fma2(A[0], w0, fma2(A[1], w1, mul2(A[2], w2)));
        u1 = fma2(A[3], w0, fma2(A[4], w1, mul2(A[5], w2)));
        u2 = fma2(A[6], w0, fma2(A[7], w1, mul2(A[8], w2)));
    }   // A dead

    // ---- Horner Taylor in coefficient space: E = sa I + sb A + sc A^2 ----
    // (a,b,c) <- (a,b,c)*A + (1/k!) I :
    //   a' = c3*c + 1/k!;  b' = a - c2*c;  c' = b + c1*c
    const float invfact[NORD + 1] = {
        1.f, 1.f, 0.5f,
        1.f/6.f, 1.f/24.f, 1.f/120.f, 1.f/720.f, 1.f/5040.f, 1.f/40320.f
    };
    ull sa = bcast(invfact[NORD]), sb = 0ULL, sc = 0ULL;
    #pragma unroll
    for (int k = NORD - 1; k >= 0; k--) {
        ull na = fma2(c3,  sc, bcast(invfact[k]));
        ull nb = fma2(nc2, sc, sa);
        ull ncc = fma2(c1, sc, sb);
        sa = na; sb = nb; sc = ncc;
    }

    // ---- NSQ squarings in coefficient space ----
    #pragma unroll
    for (int sq = 0; sq < NSQ; sq++) {
        ull bc = mul2(sb, sc);
        ull s2 = add2(bc, bc);                // 2bc
        ull cc = mul2(sc, sc);                // c^2
        ull ab = mul2(sa, sb);
        ull ab2 = add2(ab, ab);               // 2ab
        ull ac = mul2(sa, sc);
        ull ac2 = add2(ac, ac);               // 2ac
        ull na = fma2(cc, k_a, fma2(s2, c3,  mul2(sa, sa)));
        ull nb = fma2(cc, k_b, fma2(s2, nc2, ab2));
        ull ncc = fma2(cc, k_c, fma2(s2, c1, fma2(sb, sb, ac2)));
        sa = na; sb = nb; sc = ncc;
    }

    // ---- y = sa*v + sb*w + sc*u ----
    ull y0 = fma2(sa, v0, fma2(sb, w0, mul2(sc, u0)));
    ull y1 = fma2(sa, v1, fma2(sb, w1, mul2(sc, u1)));
    ull y2 = fma2(sa, v2, fma2(sb, w2, mul2(sc, u2)));

    if (full) {
        float y0a, y0b, y1a, y1b, y2a, y2b;
        upk(y0, y0a, y0b); upk(y1, y1a, y1b); upk(y2, y2a, y2b);
        float2* oq = (float2*)(out + b0 * 3);
        oq[0] = make_float2(y0a, y1a);
        oq[1] = make_float2(y2a, y0b);
        oq[2] = make_float2(y1b, y2b);
    } else {
        float ya, yb;
        float* ob = out + b0 * 3;
        upk(y0, ya, yb); ob[0] = ya;
        upk(y1, ya, yb); ob[1] = ya;
        upk(y2, ya, yb); ob[2] = ya;
    }
}

extern "C" void kernel_launch(void* const* d_in, const int* in_sizes, int n_in,
                              void* d_out, int out_size) {
    const float* x   = (const float*)d_in[0];  // [B,3,1]
    const float* c   = (const float*)d_in[1];  // [B,6]
    const float* psi = (const float*)d_in[2];  // [6,3,3]
    float* out = (float*)d_out;                // [B,3]

    int B = in_sizes[0] / 3;
    int pairs = (B + 1) / 2;
    int threads = 256;
    int blocks = (pairs + threads - 1) / threads;
    expmch5_kernel<<<blocks, threads>>>(x, c, psi, out, B);
}

// round 6
// speedup vs baseline: 1.2420x; 1.0076x over previous
#include <cuda_runtime.h>

// TransOp_expm via Cayley-Hamilton, 2 batches/thread packed f32x2.
// R6: LDS.128 psi loads (padded rows), NSQ=3 / ORDER=10, tightened squaring.

#define NSQ 3
#define NORD 10

typedef unsigned long long ull;

__device__ __forceinline__ ull pk(float lo, float hi) {
    ull r; asm("mov.b64 %0, {%1, %2};" : "=l"(r) : "f"(lo), "f"(hi)); return r;
}
__device__ __forceinline__ void upk(ull v, float& lo, float& hi) {
    asm("mov.b64 {%0, %1}, %2;" : "=f"(lo), "=f"(hi) : "l"(v));
}
__device__ __forceinline__ ull fma2(ull a, ull b, ull c) {
    ull d; asm("fma.rn.f32x2 %0, %1, %2, %3;" : "=l"(d) : "l"(a), "l"(b), "l"(c)); return d;
}
__device__ __forceinline__ ull mul2(ull a, ull b) {
    ull d; asm("mul.rn.f32x2 %0, %1, %2;" : "=l"(d) : "l"(a), "l"(b)); return d;
}
__device__ __forceinline__ ull add2(ull a, ull b) {
    ull d; asm("add.rn.f32x2 %0, %1, %2;" : "=l"(d) : "l"(a), "l"(b)); return d;
}
__device__ __forceinline__ ull bcast(float v) { return pk(v, v); }

__global__ __launch_bounds__(256, 6) void expmch6_kernel(
    const float* __restrict__ x,
    const float* __restrict__ c,
    const float* __restrict__ psi,
    float* __restrict__ out,
    int B)
{
    // psi pre-scaled by 1/2^NSQ, packed f32x2, rows padded to 10 ulls (16B-aligned)
    __shared__ __align__(16) ull s_psi[60];
    if (threadIdx.x < 60) {
        int row = threadIdx.x / 10, col = threadIdx.x % 10;
        float v = (col < 9) ? psi[row * 9 + col] * (1.0f / (float)(1 << NSQ)) : 0.0f;
        s_psi[threadIdx.x] = pk(v, v);
    }
    __syncthreads();

    int t  = blockIdx.x * blockDim.x + threadIdx.x;
    int b0 = 2 * t;
    if (b0 >= B) return;
    bool full = (b0 + 1 < B);

    // ---- load c and x early ----
    ull cm[6];
    ull v0, v1, v2;
    if (full) {
        const float4* cq = (const float4*)(c + b0 * 6);
        float4 q0 = __ldg(&cq[0]);
        float4 q1 = __ldg(&cq[1]);
        float4 q2 = __ldg(&cq[2]);
        const float2* xq = (const float2*)(x + b0 * 3);
        float2 f0 = __ldg(&xq[0]);
        float2 f1 = __ldg(&xq[1]);
        float2 f2 = __ldg(&xq[2]);
        cm[0] = pk(q0.x, q1.z);
        cm[1] = pk(q0.y, q1.w);
        cm[2] = pk(q0.z, q2.x);
        cm[3] = pk(q0.w, q2.y);
        cm[4] = pk(q1.x, q2.z);
        cm[5] = pk(q1.y, q2.w);
        v0 = pk(f0.x, f1.y);
        v1 = pk(f0.y, f2.x);
        v2 = pk(f1.x, f2.y);
    } else {
        const float* cb = c + b0 * 6;
        #pragma unroll
        for (int m = 0; m < 6; m++) { float v = __ldg(&cb[m]); cm[m] = pk(v, v); }
        const float* xb = x + b0 * 3;
        float x0 = __ldg(&xb[0]), x1 = __ldg(&xb[1]), x2 = __ldg(&xb[2]);
        v0 = pk(x0, x0); v1 = pk(x1, x1); v2 = pk(x2, x2);
    }

    // ---- invariants + matvecs (A dies at end of scope) ----
    ull c1, nc2, c3, k_a, k_b, k_c, c1x2, nc2x2, c3x2;
    ull w0, w1, w2, u0, u1, u2;
    {
        const ull NEG1 = bcast(-1.0f);
        ull A[9];
        {
            const ulonglong2* sv = (const ulonglong2*)s_psi;
            // m = 0
            {
                ulonglong2 p0 = sv[0], p1 = sv[1], p2 = sv[2], p3 = sv[3];
                ull p8 = s_psi[8];
                A[0] = mul2(cm[0], p0.x); A[1] = mul2(cm[0], p0.y);
                A[2] = mul2(cm[0], p1.x); A[3] = mul2(cm[0], p1.y);
                A[4] = mul2(cm[0], p2.x); A[5] = mul2(cm[0], p2.y);
                A[6] = mul2(cm[0], p3.x); A[7] = mul2(cm[0], p3.y);
                A[8] = mul2(cm[0], p8);
            }
            #pragma unroll
            for (int m = 1; m < 6; m++) {
                ulonglong2 p0 = sv[m * 5 + 0], p1 = sv[m * 5 + 1];
                ulonglong2 p2 = sv[m * 5 + 2], p3 = sv[m * 5 + 3];
                ull p8 = s_psi[m * 10 + 8];
                A[0] = fma2(cm[m], p0.x, A[0]); A[1] = fma2(cm[m], p0.y, A[1]);
                A[2] = fma2(cm[m], p1.x, A[2]); A[3] = fma2(cm[m], p1.y, A[3]);
                A[4] = fma2(cm[m], p2.x, A[4]); A[5] = fma2(cm[m], p2.y, A[5]);
                A[6] = fma2(cm[m], p3.x, A[6]); A[7] = fma2(cm[m], p3.y, A[7]);
                A[8] = fma2(cm[m], p8, A[8]);
            }
        }

        c1 = add2(add2(A[0], A[4]), A[8]);
        ull d0 = fma2(A[0], A[0], fma2(A[1], A[3], mul2(A[2], A[6])));
        ull d1 = fma2(A[3], A[1], fma2(A[4], A[4], mul2(A[5], A[7])));
        ull d2 = fma2(A[6], A[2], fma2(A[7], A[5], mul2(A[8], A[8])));
        ull trA2 = add2(add2(d0, d1), d2);
        ull c1sq = mul2(c1, c1);
        nc2 = mul2(fma2(c1sq, NEG1, trA2), bcast(0.5f));           // -c2
        ull m0  = fma2(mul2(A[5], A[7]), NEG1, mul2(A[4], A[8]));
        ull m1n = fma2(mul2(A[3], A[8]), NEG1, mul2(A[5], A[6]));
        ull m2  = fma2(mul2(A[4], A[6]), NEG1, mul2(A[3], A[7]));
        c3  = fma2(A[0], m0, fma2(A[1], m1n, mul2(A[2], m2)));
        k_a = mul2(c1, c3);
        k_b = fma2(c1, nc2, c3);
        k_c = add2(c1sq, nc2);
        c1x2  = add2(c1, c1);
        nc2x2 = add2(nc2, nc2);
        c3x2  = add2(c3, c3);

        w0 = fma2(A[0], v0, fma2(A[1], v1, mul2(A[2], v2)));
        w1 = fma2(A[3], v0, fma2(A[4], v1, mul2(A[5], v2)));
        w2 = fma2(A[6], v0, fma2(A[7], v1, mul2(A[8], v2)));
        u0 = fma2(A[0], w0, fma2(A[1], w1, mul2(A[2], w2)));
        u1 = fma2(A[3], w0, fma2(A[4], w1, mul2(A[5], w2)));
        u2 = fma2(A[6], w0, fma2(A[7], w1, mul2(A[8], w2)));
    }

    // ---- Horner Taylor in coefficient space: E = sa I + sb A + sc A^2 ----
    const float invfact[NORD + 1] = {
        1.f, 1.f, 0.5f, 1.f/6.f, 1.f/24.f, 1.f/120.f, 1.f/720.f,
        1.f/5040.f, 1.f/40320.f, 1.f/362880.f, 1.f/3628800.f
    };
    ull sa = bcast(invfact[NORD]), sb = 0ULL, sc = 0ULL;
    #pragma unroll
    for (int k = NORD - 1; k >= 0; k--) {
        ull na  = fma2(c3,  sc, bcast(invfact[k]));
        ull nb  = fma2(nc2, sc, sa);
        ull ncc = fma2(c1,  sc, sb);
        sa = na; sb = nb; sc = ncc;
    }

    // ---- NSQ squarings in coefficient space ----
    // E^2 = (sa^2 + 2bc*c3 + cc*k_a) I + (2ab + 2bc*(-c2) + cc*k_b) A
    //       + (sb^2 + 2ac + 2bc*c1 + cc*k_c) A^2
    #pragma unroll
    for (int sq = 0; sq < NSQ; sq++) {
        ull bc = mul2(sb, sc);
        ull cc = mul2(sc, sc);
        ull ab = mul2(sa, sb);
        ull ac = mul2(sa, sc);
        ull na  = fma2(cc, k_a, fma2(bc, c3x2,  mul2(sa, sa)));
        ull nb  = fma2(cc, k_b, fma2(bc, nc2x2, add2(ab, ab)));
        ull ncc = fma2(cc, k_c, fma2(bc, c1x2,  fma2(sb, sb, add2(ac, ac))));
        sa = na; sb = nb; sc = ncc;
    }

    // ---- y = sa*v + sb*w + sc*u ----
    ull y0 = fma2(sa, v0, fma2(sb, w0, mul2(sc, u0)));
    ull y1 = fma2(sa, v1, fma2(sb, w1, mul2(sc, u1)));
    ull y2 = fma2(sa, v2, fma2(sb, w2, mul2(sc, u2)));

    if (full) {
        float y0a, y0b, y1a, y1b, y2a, y2b;
        upk(y0, y0a, y0b); upk(y1, y1a, y1b); upk(y2, y2a, y2b);
        float2* oq = (float2*)(out + b0 * 3);
        oq[0] = make_float2(y0a, y1a);
        oq[1] = make_float2(y2a, y0b);
        oq[2] = make_float2(y1b, y2b);
    } else {
        float ya, yb;
        float* ob = out + b0 * 3;
        upk(y0, ya, yb); ob[0] = ya;
        upk(y1, ya, yb); ob[1] = ya;
        upk(y2, ya, yb); ob[2] = ya;
    }
}

extern "C" void kernel_launch(void* const* d_in, const int* in_sizes, int n_in,
                              void* d_out, int out_size) {
    const float* x   = (const float*)d_in[0];  // [B,3,1]
    const float* c   = (const float*)d_in[1];  // [B,6]
    const float* psi = (const float*)d_in[2];  // [6,3,3]
    float* out = (float*)d_out;                // [B,3]

    int B = in_sizes[0] / 3;
    int pairs = (B + 1) / 2;
    int threads = 256;
    int blocks = (pairs + threads - 1) / threads;
    expmch6_kernel<<<blocks, threads>>>(x, c, psi, out, B);
}